// round 11
// baseline (speedup 1.0000x reference)
#include <cuda_runtime.h>
#include <cuda_bf16.h>
#include <cstdint>

#define NODES   50000
#define MAXE    800000
#define INDIM   128
#define HH      256     // HEADS*HIDDEN
#define HEADS   4
#define HID     64
#define EPSV    1e-5f
#define NEG     0.2f

// ---------------- PTX helpers (base sm_103-safe) ----------------
__device__ __forceinline__ uint32_t smem_to_u32(const void* p) {
    uint32_t a;
    asm("{ .reg .u64 t; cvta.to.shared.u64 t, %1; cvt.u32.u64 %0, t; }" : "=r"(a) : "l"(p));
    return a;
}
#define LDSM_X4(r0, r1, r2, r3, addr) \
    asm volatile("ldmatrix.sync.aligned.m8n8.x4.shared.b16 {%0,%1,%2,%3}, [%4];" \
        : "=r"(r0), "=r"(r1), "=r"(r2), "=r"(r3) : "r"(addr))
#define MMA_BF16(d, a, b) \
    asm volatile("mma.sync.aligned.m16n8k16.row.col.f32.bf16.bf16.f32 " \
        "{%0,%1,%2,%3}, {%4,%5,%6,%7}, {%8,%9}, {%0,%1,%2,%3};" \
        : "+f"((d)[0]), "+f"((d)[1]), "+f"((d)[2]), "+f"((d)[3]) \
        : "r"((a)[0]), "r"((a)[1]), "r"((a)[2]), "r"((a)[3]), "r"((b)[0]), "r"((b)[1]))

// -------- device scratch (no allocation allowed) --------
__device__ float g_hl [NODES * HH];
__device__ float g_agg[NODES * HH];
__device__ float g_asrc[NODES * HEADS];
__device__ float g_adst[NODES * HEADS];
__device__ float g_sums[512];
__device__ float g_scale[256];
__device__ float g_shift[256];
__device__ float g_mean[256];
__device__ float g_rowbias[256];
__device__ uint16_t g_Wt_hi[256 * 256];     // W^T split bf16 hi [n][k]
__device__ uint16_t g_Wt_lo[256 * 256];     // bf16 lo residual  [n][k]
__device__ uint16_t g_xh[NODES * INDIM];    // x split hi
__device__ uint16_t g_xl[NODES * INDIM];    // x split lo
__device__ uint16_t g_h2h[NODES * HH];      // post-BN2+ReLU split hi
__device__ uint16_t g_h2l[NODES * HH];      // split lo
// CSR build scratch
__device__ int g_deg[NODES];
__device__ int g_rowptr[NODES];
__device__ int g_cursor[NODES];
__device__ int g_bsums[256];
__device__ int g_csr[MAXE + NODES];

// ---------------- utility kernels ----------------
__global__ void k_clear(float* __restrict__ p, int n) {
    int i = blockIdx.x * blockDim.x + threadIdx.x;
    if (i < n) p[i] = 0.f;
}

__global__ void k_colstats(const float* __restrict__ x, int n, int C,
                           float* __restrict__ sums, float* __restrict__ sumsq) {
    int c = threadIdx.x;
    float s = 0.f, s2 = 0.f;
    for (int r = blockIdx.x; r < n; r += gridDim.x) {
        float v = x[(size_t)r * C + c];
        s += v; s2 += v * v;
    }
    atomicAdd(&sums[c], s);
    atomicAdd(&sumsq[c], s2);
}

__global__ void k_bnfinal(const float* __restrict__ gamma, const float* __restrict__ beta,
                          int C, int n, int fold) {
    int c = threadIdx.x;
    if (c >= C) return;
    float mean = g_sums[c] / (float)n;
    float var  = g_sums[256 + c] / (float)n - mean * mean;
    float sc   = rsqrtf(var + EPSV) * gamma[c];
    g_scale[c] = sc;
    if (fold) g_shift[c] = beta[c] - mean * sc;
    else      g_mean[c]  = mean;
}

__global__ void k_rowbias(const float* __restrict__ W, int K) {
    __shared__ float sh[128];
    int j = blockIdx.x, t = threadIdx.x;
    float s = 0.f;
    for (int k = t; k < K; k += 128) s += g_shift[k] * W[(size_t)k * HH + j];
    sh[t] = s; __syncthreads();
    for (int off = 64; off; off >>= 1) { if (t < off) sh[t] += sh[t + off]; __syncthreads(); }
    if (t == 0) g_rowbias[j] = sh[0];
}

// ---------------- split helpers ----------------
__device__ __forceinline__ void splitf(float x, uint16_t& h, uint16_t& l) {
    __nv_bfloat16 bh = __float2bfloat16(x);
    float r = x - __bfloat162float(bh);
    __nv_bfloat16 bl = __float2bfloat16(r);
    h = __bfloat16_as_ushort(bh);
    l = __bfloat16_as_ushort(bl);
}

__global__ void k_prepw(const float* __restrict__ W, int K, const float* __restrict__ colscale) {
    int idx = blockIdx.x * blockDim.x + threadIdx.x;   // idx = n*K + k
    if (idx >= 256 * K) return;
    int n = idx / K, k = idx - n * K;
    float v = W[(size_t)k * 256 + n];
    if (colscale) v *= colscale[k];
    uint16_t h, l;
    splitf(v, h, l);
    g_Wt_hi[idx] = h;
    g_Wt_lo[idx] = l;
}

__global__ void k_prepx(const float* __restrict__ x, int total) {
    int i = blockIdx.x * blockDim.x + threadIdx.x;
    if (i >= total) return;
    uint16_t h, l;
    splitf(x[i], h, l);
    g_xh[i] = h;
    g_xl[i] = l;
}

// ---------------- HMMA GEMM, cp.async double-buffered, attn fused ----------------
// C[M,256] = A @ W (+rowbias); also writes g_asrc/g_adst dots for attention.
// Block 256 thr = 8 warps (4M x 2N); blocktile 128x128; K chunks of 32; 2-stage cp.async.
#define SPITCH 40
#define ARR_BYTES   10240      // 128 rows * 80 B
#define STAGE_BYTES 40960      // 4 arrays (Ah,Al,Bh,Bl)
#define GSMEM_TOTAL 81920      // 2 stages

__global__ __launch_bounds__(256)
void k_mmagemm(const __nv_bfloat16* __restrict__ Ah, const __nv_bfloat16* __restrict__ Al,
               float* __restrict__ C, int M, int K,
               const float* __restrict__ rowbias,
               const float* __restrict__ atts, const float* __restrict__ attd) {
    extern __shared__ __align__(16) char smem[];
    const int tid = threadIdx.x, lane = tid & 31, wid = tid >> 5;
    const int warpM = wid >> 1, warpN = wid & 1;
    const int rowBase = blockIdx.y * 128;
    const int colBase = blockIdx.x * 128;
    const uint32_t sb = smem_to_u32(smem);

    const int nch = K >> 5;
    float acc[2][8][4] = {};

    auto stage_load = [&](int ch) {
        uint32_t base = sb + (ch & 1) * STAGE_BYTES;
        int k0 = ch << 5;
#pragma unroll
        for (int it = 0; it < 8; it++) {
            int i = tid + it * 256;
            int arr = i >> 9, rem = i & 511, r = rem >> 2, q = rem & 3;
            uint32_t dst = base + arr * ARR_BYTES + r * 80 + q * 16;
            const __nv_bfloat16* src;
            int sz = 16;
            if (arr < 2) {
                int gr = rowBase + r;
                if (gr >= M) { sz = 0; gr = M - 1; }
                src = (arr ? Al : Ah) + (size_t)gr * K + k0 + q * 8;
            } else {
                int gn = colBase + r;
                const uint16_t* W = (arr == 3) ? g_Wt_lo : g_Wt_hi;
                src = (const __nv_bfloat16*)(W + (size_t)gn * K + k0 + q * 8);
            }
            asm volatile("cp.async.cg.shared.global [%0], [%1], 16, %2;"
                         :: "r"(dst), "l"(src), "r"(sz) : "memory");
        }
        asm volatile("cp.async.commit_group;" ::: "memory");
    };

    stage_load(0);

    for (int ch = 0; ch < nch; ch++) {
        if (ch + 1 < nch) {
            stage_load(ch + 1);
            asm volatile("cp.async.wait_group 1;" ::: "memory");
        } else {
            asm volatile("cp.async.wait_group 0;" ::: "memory");
        }
        __syncthreads();

        uint32_t base = sb + (ch & 1) * STAGE_BYTES;
        uint32_t sAh = base, sAl = base + ARR_BYTES;
        uint32_t sBh = base + 2 * ARR_BYTES, sBl = base + 3 * ARR_BYTES;

#pragma unroll
        for (int s = 0; s < 2; s++) {
            uint32_t ah[2][4], al[2][4];
#pragma unroll
            for (int mt = 0; mt < 2; mt++) {
                int rA = warpM * 32 + mt * 16 + (lane & 15);
                int kA = s * 16 + ((lane & 16) ? 8 : 0);
                uint32_t byteOff = (uint32_t)(rA * SPITCH + kA) * 2;
                LDSM_X4(ah[mt][0], ah[mt][1], ah[mt][2], ah[mt][3], sAh + byteOff);
                LDSM_X4(al[mt][0], al[mt][1], al[mt][2], al[mt][3], sAl + byteOff);
            }
            uint32_t bh[8][2], bl[8][2];
#pragma unroll
            for (int p = 0; p < 4; p++) {
                int g = lane >> 3;
                int nB = warpN * 64 + p * 16 + ((g & 2) ? 8 : 0) + (lane & 7);
                int kB = s * 16 + ((g & 1) ? 8 : 0);
                uint32_t byteOff = (uint32_t)(nB * SPITCH + kB) * 2;
                LDSM_X4(bh[2*p][0], bh[2*p][1], bh[2*p+1][0], bh[2*p+1][1], sBh + byteOff);
                LDSM_X4(bl[2*p][0], bl[2*p][1], bl[2*p+1][0], bl[2*p+1][1], sBl + byteOff);
            }
#pragma unroll
            for (int mt = 0; mt < 2; mt++)
#pragma unroll
                for (int nt = 0; nt < 8; nt++) {
                    MMA_BF16(acc[mt][nt], ah[mt], bh[nt]);
                    MMA_BF16(acc[mt][nt], ah[mt], bl[nt]);
                    MMA_BF16(acc[mt][nt], al[mt], bh[nt]);
                }
        }
        __syncthreads();
    }

    // ---- epilogue: rowbias, store, fused attention dots ----
    if (rowbias) {
#pragma unroll
        for (int nt = 0; nt < 8; nt++) {
            int col = colBase + warpN * 64 + nt * 8 + (lane & 3) * 2;
            float b0 = rowbias[col], b1 = rowbias[col + 1];
#pragma unroll
            for (int mt = 0; mt < 2; mt++) {
                acc[mt][nt][0] += b0; acc[mt][nt][1] += b1;
                acc[mt][nt][2] += b0; acc[mt][nt][3] += b1;
            }
        }
    }
#pragma unroll
    for (int mt = 0; mt < 2; mt++) {
        int r0 = rowBase + warpM * 32 + mt * 16 + (lane >> 2);
#pragma unroll
        for (int half = 0; half < 2; half++) {
            int row = r0 + half * 8;
            if (row >= M) continue;
#pragma unroll
            for (int nt = 0; nt < 8; nt++) {
                int col = colBase + warpN * 64 + nt * 8 + (lane & 3) * 2;
                *(float2*)(C + (size_t)row * 256 + col) =
                    make_float2(acc[mt][nt][half * 2], acc[mt][nt][half * 2 + 1]);
            }
        }
    }
    // attention: this warp's 64 cols == head h's span
    {
        int h = (colBase >> 6) + warpN;
        const float* As_v = atts + h * 64;
        const float* Ad_v = attd + h * 64;
#pragma unroll
        for (int mt = 0; mt < 2; mt++) {
#pragma unroll
            for (int half = 0; half < 2; half++) {
                float ds = 0.f, dd = 0.f;
#pragma unroll
                for (int nt = 0; nt < 8; nt++) {
                    int cw = nt * 8 + (lane & 3) * 2;
                    float v0 = acc[mt][nt][half * 2], v1 = acc[mt][nt][half * 2 + 1];
                    ds += v0 * As_v[cw] + v1 * As_v[cw + 1];
                    dd += v0 * Ad_v[cw] + v1 * Ad_v[cw + 1];
                }
                ds += __shfl_xor_sync(0xffffffffu, ds, 1);
                ds += __shfl_xor_sync(0xffffffffu, ds, 2);
                dd += __shfl_xor_sync(0xffffffffu, dd, 1);
                dd += __shfl_xor_sync(0xffffffffu, dd, 2);
                int row = rowBase + warpM * 32 + mt * 16 + half * 8 + (lane >> 2);
                if ((lane & 3) == 0 && row < M) {
                    g_asrc[row * HEADS + h] = ds;
                    g_adst[row * HEADS + h] = dd;
                }
            }
        }
    }
}

// ---------------- CSR build ----------------
__global__ void k_deginit(int n) {
    int i = blockIdx.x * blockDim.x + threadIdx.x;
    if (i < n) g_deg[i] = 1;
}
__global__ void k_hist(const int* __restrict__ dstp, int E) {
    int i = blockIdx.x * blockDim.x + threadIdx.x;
    if (i < E) atomicAdd(&g_deg[dstp[i]], 1);
}
__global__ void k_scan1(int n) {
    __shared__ int sh[256];
    int tid = threadIdx.x;
    int i = blockIdx.x * 256 + tid;
    int v = (i < n) ? g_deg[i] : 0;
    sh[tid] = v; __syncthreads();
    for (int off = 1; off < 256; off <<= 1) {
        int t = (tid >= off) ? sh[tid - off] : 0;
        __syncthreads();
        sh[tid] += t;
        __syncthreads();
    }
    if (i < n) g_rowptr[i] = sh[tid] - v;
    if (tid == 255) g_bsums[blockIdx.x] = sh[255];
}
__global__ void k_scan2(int nb) {
    __shared__ int sh[256];
    int tid = threadIdx.x;
    int v = (tid < nb) ? g_bsums[tid] : 0;
    sh[tid] = v; __syncthreads();
    for (int off = 1; off < 256; off <<= 1) {
        int t = (tid >= off) ? sh[tid - off] : 0;
        __syncthreads();
        sh[tid] += t;
        __syncthreads();
    }
    if (tid < nb) g_bsums[tid] = sh[tid] - v;
}
__global__ void k_scan3(int n) {
    int i = blockIdx.x * 256 + threadIdx.x;
    if (i < n) {
        int r = g_rowptr[i] + g_bsums[blockIdx.x];
        g_rowptr[i] = r;
        g_cursor[i] = r;
    }
}
__global__ void k_scatter(const int* __restrict__ srcp, const int* __restrict__ dstp,
                          int E, int n) {
    int i = blockIdx.x * blockDim.x + threadIdx.x;
    int Et = E + n;
    if (i >= Et) return;
    int s, d;
    if (i < E) { s = srcp[i]; d = dstp[i]; }
    else       { s = d = i - E; }
    int pos = atomicAdd(&g_cursor[d], 1);
    g_csr[pos] = s;
}

// ---------------- gather aggregation: warp per dst node ----------------
// LAYER=1: g_agg[d][256] = normalized weighted sum + bias; fused BN2 col-stats.
// LAYER=2: out[d][64] = mean over heads + bias.
template <int LAYER>
__global__ void k_gather(const float* __restrict__ bias, float* __restrict__ out, int n) {
    __shared__ float ssum[256], ssq[256];
    int tid = threadIdx.x;
    if (LAYER == 1) {
        ssum[tid] = 0.f; ssq[tid] = 0.f;
        __syncthreads();
    }
    int d = (blockIdx.x * blockDim.x + tid) >> 5;
    int lane = tid & 31;

    if (d < n) {
        float adv = 0.f;
        if (lane < HEADS) adv = g_adst[d * HEADS + lane];

        int e   = g_rowptr[d];
        int end = g_cursor[d];

        float acc[8] = {};
        float den = 0.f;
#pragma unroll 2
        for (; e < end; e++) {
            int s = g_csr[e];
            float wl = 0.f;
            if (lane < HEADS) {
                float a = g_asrc[s * HEADS + lane] + adv;
                a = (a > 0.f) ? a : NEG * a;
                wl = __expf(a);
                den += wl;
            }
            const float* hr = g_hl + (size_t)s * HH;
#pragma unroll
            for (int h = 0; h < HEADS; h++) {
                float wh = __shfl_sync(0xffffffffu, wl, h);
                acc[2*h]   += wh * __ldg(hr + h * 64 + lane);
                acc[2*h+1] += wh * __ldg(hr + h * 64 + 32 + lane);
            }
        }
        float dv[4];
#pragma unroll
        for (int h = 0; h < HEADS; h++) dv[h] = __shfl_sync(0xffffffffu, den, h);

        if (LAYER == 1) {
            float* orow = g_agg + (size_t)d * HH;
#pragma unroll
            for (int h = 0; h < HEADS; h++) {
                int c0 = h * 64 + lane;
                float v0 = acc[2*h]   / dv[h] + bias[c0];
                float v1 = acc[2*h+1] / dv[h] + bias[c0 + 32];
                orow[c0]      = v0;
                orow[c0 + 32] = v1;
                atomicAdd(&ssum[c0], v0);      atomicAdd(&ssq[c0], v0 * v0);
                atomicAdd(&ssum[c0 + 32], v1); atomicAdd(&ssq[c0 + 32], v1 * v1);
            }
        } else {
            float v0 = 0.f, v1 = 0.f;
#pragma unroll
            for (int h = 0; h < HEADS; h++) {
                v0 += acc[2*h]   / dv[h];
                v1 += acc[2*h+1] / dv[h];
            }
            out[d * HID + lane]      = 0.25f * v0 + bias[lane];
            out[d * HID + lane + 32] = 0.25f * v1 + bias[lane + 32];
        }
    }
    if (LAYER == 1) {
        __syncthreads();
        atomicAdd(&g_sums[tid], ssum[tid]);
        atomicAdd(&g_sums[256 + tid], ssq[tid]);
    }
}

// BN2 normalize + ReLU -> split bf16 (feeds GEMM2 directly)
__global__ void k_bnrelu(const float* __restrict__ beta, int n) {
    size_t i = (size_t)blockIdx.x * blockDim.x + threadIdx.x;
    if (i >= (size_t)n * HH) return;
    int c = (int)(i & 255);
    float v = (g_agg[i] - g_mean[c]) * g_scale[c] + beta[c];
    v = (v > 0.f) ? v : 0.f;
    uint16_t h, l;
    splitf(v, h, l);
    g_h2h[i] = h;
    g_h2l[i] = l;
}

// ---------------- host launcher ----------------
extern "C" void kernel_launch(void* const* d_in, const int* in_sizes, int n_in,
                              void* d_out, int out_size) {
    const float* x        = (const float*)d_in[0];
    const int*   ei       = (const int*)d_in[1];      // int32 (JAX x64 disabled)
    const float* gamma1   = (const float*)d_in[2];
    const float* beta1    = (const float*)d_in[3];
    const float* W1       = (const float*)d_in[4];
    const float* att_src1 = (const float*)d_in[5];
    const float* att_dst1 = (const float*)d_in[6];
    const float* bias1    = (const float*)d_in[7];
    const float* gamma2   = (const float*)d_in[8];
    const float* beta2    = (const float*)d_in[9];
    const float* W2       = (const float*)d_in[10];
    const float* att_src2 = (const float*)d_in[11];
    const float* att_dst2 = (const float*)d_in[12];
    const float* bias2    = (const float*)d_in[13];

    int n = in_sizes[0] / INDIM;
    int E = in_sizes[1] / 2;
    const int* srcp = ei;
    const int* dstp = ei + E;
    float* out = (float*)d_out;

    float *p_hl, *p_sums, *p_scale, *p_rowbias;
    cudaGetSymbolAddress((void**)&p_hl,      g_hl);
    cudaGetSymbolAddress((void**)&p_sums,    g_sums);
    cudaGetSymbolAddress((void**)&p_scale,   g_scale);
    cudaGetSymbolAddress((void**)&p_rowbias, g_rowbias);
    __nv_bfloat16 *p_xh, *p_xl, *p_h2h, *p_h2l;
    cudaGetSymbolAddress((void**)&p_xh,  g_xh);
    cudaGetSymbolAddress((void**)&p_xl,  g_xl);
    cudaGetSymbolAddress((void**)&p_h2h, g_h2h);
    cudaGetSymbolAddress((void**)&p_h2l, g_h2l);

    cudaFuncSetAttribute(k_mmagemm, cudaFuncAttributeMaxDynamicSharedMemorySize, GSMEM_TOTAL);

    int Et = E + n;
    int featElems = n * HH;
    int scanBlocks = (n + 255) / 256;
    dim3 gemmGrid(2, (n + 127) / 128);

    // ---- CSR build ----
    k_deginit<<<scanBlocks, 256>>>(n);
    k_hist<<<(E + 255) / 256, 256>>>(dstp, E);
    k_scan1<<<scanBlocks, 256>>>(n);
    k_scan2<<<1, 256>>>(scanBlocks);
    k_scan3<<<scanBlocks, 256>>>(n);
    k_scatter<<<(Et + 255) / 256, 256>>>(srcp, dstp, E, n);

    // ---- BN1 stats (folded into GEMM1 via W colscale + rowbias) ----
    k_clear<<<2, 256>>>(p_sums, 512);
    k_colstats<<<512, INDIM>>>(x, n, INDIM, p_sums, p_sums + 256);
    k_bnfinal<<<1, INDIM>>>(gamma1, beta1, INDIM, n, 1);
    k_rowbias<<<HH, 128>>>(W1, INDIM);

    // ---- GAT1 ----
    k_prepx<<<(n * INDIM + 255) / 256, 256>>>(x, n * INDIM);
    k_prepw<<<(256 * INDIM + 255) / 256, 256>>>(W1, INDIM, p_scale);
    k_clear<<<2, 256>>>(p_sums, 512);   // for fused BN2 stats
    k_mmagemm<<<gemmGrid, 256, GSMEM_TOTAL>>>(p_xh, p_xl, p_hl, n, INDIM,
                                              p_rowbias, att_src1, att_dst1);
    k_gather<1><<<(n * 32 + 255) / 256, 256>>>(bias1, nullptr, n);

    // ---- BN2 + ReLU (writes split bf16 h2) ----
    k_bnfinal<<<1, HH>>>(gamma2, beta2, HH, n, 0);
    k_bnrelu<<<(featElems + 255) / 256, 256>>>(beta2, n);

    // ---- GAT2 ----
    k_prepw<<<(256 * HH + 255) / 256, 256>>>(W2, HH, nullptr);
    k_mmagemm<<<gemmGrid, 256, GSMEM_TOTAL>>>(p_h2h, p_h2l, p_hl, n, HH,
                                              nullptr, att_src2, att_dst2);
    k_gather<2><<<(n * 32 + 255) / 256, 256>>>(bias2, out, n);
}

// round 13
// speedup vs baseline: 1.2385x; 1.2385x over previous
#include <cuda_runtime.h>
#include <cuda_bf16.h>
#include <cstdint>

#define NODES   50000
#define MAXE    800000
#define INDIM   128
#define HH      256     // HEADS*HIDDEN
#define HEADS   4
#define HID     64
#define EPSV    1e-5f
#define NEG     0.2f

// ---------------- PTX helpers (base sm_103-safe) ----------------
__device__ __forceinline__ uint32_t smem_to_u32(const void* p) {
    uint32_t a;
    asm("{ .reg .u64 t; cvta.to.shared.u64 t, %1; cvt.u32.u64 %0, t; }" : "=r"(a) : "l"(p));
    return a;
}
#define LDSM_X4(r0, r1, r2, r3, addr) \
    asm volatile("ldmatrix.sync.aligned.m8n8.x4.shared.b16 {%0,%1,%2,%3}, [%4];" \
        : "=r"(r0), "=r"(r1), "=r"(r2), "=r"(r3) : "r"(addr))
#define MMA_BF16(d, a, b) \
    asm volatile("mma.sync.aligned.m16n8k16.row.col.f32.bf16.bf16.f32 " \
        "{%0,%1,%2,%3}, {%4,%5,%6,%7}, {%8,%9}, {%0,%1,%2,%3};" \
        : "+f"((d)[0]), "+f"((d)[1]), "+f"((d)[2]), "+f"((d)[3]) \
        : "r"((a)[0]), "r"((a)[1]), "r"((a)[2]), "r"((a)[3]), "r"((b)[0]), "r"((b)[1]))

// -------- device scratch (no allocation allowed) --------
__device__ float g_hl [NODES * HH];
__device__ float g_agg[NODES * HH];
__device__ float g_asrc[NODES * HEADS];
__device__ float g_adst[NODES * HEADS];
__device__ float g_sums[512];
__device__ float g_scale[256];
__device__ float g_shift[256];
__device__ float g_mean[256];
__device__ float g_rowbias[256];
__device__ uint16_t g_Wt_hi[256 * 256];     // W^T split bf16 hi [n][k]
__device__ uint16_t g_Wt_lo[256 * 256];     // bf16 lo residual  [n][k]
__device__ uint16_t g_xh[NODES * INDIM];    // x split hi
__device__ uint16_t g_xl[NODES * INDIM];    // x split lo
__device__ uint16_t g_h2h[NODES * HH];      // post-BN2+ReLU split hi
__device__ uint16_t g_h2l[NODES * HH];      // split lo
// CSR build scratch
__device__ int g_deg[NODES];
__device__ int g_rowptr[NODES];
__device__ int g_cursor[NODES];
__device__ int g_bsums[256];
__device__ int g_csr[MAXE + NODES];

// ---------------- utility kernels ----------------
__global__ void k_clear(float* __restrict__ p, int n) {
    int i = blockIdx.x * blockDim.x + threadIdx.x;
    if (i < n) p[i] = 0.f;
}

__global__ void k_colstats(const float* __restrict__ x, int n, int C,
                           float* __restrict__ sums, float* __restrict__ sumsq) {
    int c = threadIdx.x;
    float s = 0.f, s2 = 0.f;
    for (int r = blockIdx.x; r < n; r += gridDim.x) {
        float v = x[(size_t)r * C + c];
        s += v; s2 += v * v;
    }
    atomicAdd(&sums[c], s);
    atomicAdd(&sumsq[c], s2);
}

__global__ void k_bnfinal(const float* __restrict__ gamma, const float* __restrict__ beta,
                          int C, int n, int fold) {
    int c = threadIdx.x;
    if (c >= C) return;
    float mean = g_sums[c] / (float)n;
    float var  = g_sums[256 + c] / (float)n - mean * mean;
    float sc   = rsqrtf(var + EPSV) * gamma[c];
    g_scale[c] = sc;
    if (fold) g_shift[c] = beta[c] - mean * sc;
    else      g_mean[c]  = mean;
}

__global__ void k_rowbias(const float* __restrict__ W, int K) {
    __shared__ float sh[128];
    int j = blockIdx.x, t = threadIdx.x;
    float s = 0.f;
    for (int k = t; k < K; k += 128) s += g_shift[k] * W[(size_t)k * HH + j];
    sh[t] = s; __syncthreads();
    for (int off = 64; off; off >>= 1) { if (t < off) sh[t] += sh[t + off]; __syncthreads(); }
    if (t == 0) g_rowbias[j] = sh[0];
}

// ---------------- split helpers ----------------
__device__ __forceinline__ void splitf(float x, uint16_t& h, uint16_t& l) {
    __nv_bfloat16 bh = __float2bfloat16(x);
    float r = x - __bfloat162float(bh);
    __nv_bfloat16 bl = __float2bfloat16(r);
    h = __bfloat16_as_ushort(bh);
    l = __bfloat16_as_ushort(bl);
}

__global__ void k_prepw(const float* __restrict__ W, int K, const float* __restrict__ colscale) {
    int idx = blockIdx.x * blockDim.x + threadIdx.x;   // idx = n*K + k
    if (idx >= 256 * K) return;
    int n = idx / K, k = idx - n * K;
    float v = W[(size_t)k * 256 + n];
    if (colscale) v *= colscale[k];
    uint16_t h, l;
    splitf(v, h, l);
    g_Wt_hi[idx] = h;
    g_Wt_lo[idx] = l;
}

__global__ void k_prepx(const float* __restrict__ x, int total) {
    int i = blockIdx.x * blockDim.x + threadIdx.x;
    if (i >= total) return;
    uint16_t h, l;
    splitf(x[i], h, l);
    g_xh[i] = h;
    g_xl[i] = l;
}

// ---------------- HMMA GEMM (R8 structure: static smem, sync staging, 5 CTAs/SM) ----
// Inputs pre-split bf16 hi/lo. C[M,256] = A @ W (+rowbias); attn dots fused in epilogue.
// Block 256 thr = 8 warps (4M x 2N); blocktile 128x128; K chunks of 32.
#define SPITCH 40

__global__ __launch_bounds__(256)
void k_mmagemm(const uint16_t* __restrict__ Ah, const uint16_t* __restrict__ Al,
               float* __restrict__ C, int M, int K,
               const float* __restrict__ rowbias,
               const float* __restrict__ atts, const float* __restrict__ attd) {
    __shared__ __align__(16) uint16_t As_hi[128 * SPITCH];
    __shared__ __align__(16) uint16_t As_lo[128 * SPITCH];
    __shared__ __align__(16) uint16_t Bs_hi[128 * SPITCH];
    __shared__ __align__(16) uint16_t Bs_lo[128 * SPITCH];

    const int tid = threadIdx.x, lane = tid & 31, wid = tid >> 5;
    const int warpM = wid >> 1, warpN = wid & 1;
    const int rowBase = blockIdx.y * 128;
    const int colBase = blockIdx.x * 128;

    const uint32_t sAh = smem_to_u32(As_hi), sAl = smem_to_u32(As_lo);
    const uint32_t sBh = smem_to_u32(Bs_hi), sBl = smem_to_u32(Bs_lo);

    float acc[2][8][4] = {};

    for (int k0 = 0; k0 < K; k0 += 32) {
        // ---- stage A chunk: 128 rows x 32 k, bf16 hi/lo (uint2 = 4 halfs) ----
        for (int i = tid; i < 128 * 8; i += 256) {
            int r = i >> 3, q = i & 7;
            int gr = rowBase + r;
            uint2 vh = make_uint2(0u, 0u), vl = make_uint2(0u, 0u);
            if (gr < M) {
                size_t gofs = (size_t)gr * K + k0 + q * 4;
                vh = *(const uint2*)(Ah + gofs);
                vl = *(const uint2*)(Al + gofs);
            }
            int off = r * SPITCH + q * 4;
            *(uint2*)(As_hi + off) = vh;
            *(uint2*)(As_lo + off) = vl;
        }
        // ---- stage B chunk: 128 n-rows x 32 k ----
        for (int i = tid; i < 128 * 8; i += 256) {
            int n = i >> 3, q = i & 7;
            size_t gofs = (size_t)(colBase + n) * K + k0 + q * 4;
            uint2 vh = *(const uint2*)(g_Wt_hi + gofs);
            uint2 vl = *(const uint2*)(g_Wt_lo + gofs);
            int off = n * SPITCH + q * 4;
            *(uint2*)(Bs_hi + off) = vh;
            *(uint2*)(Bs_lo + off) = vl;
        }
        __syncthreads();

#pragma unroll
        for (int s = 0; s < 2; s++) {
            uint32_t ah[2][4], al[2][4];
#pragma unroll
            for (int mt = 0; mt < 2; mt++) {
                int rA = warpM * 32 + mt * 16 + (lane & 15);
                int kA = s * 16 + ((lane & 16) ? 8 : 0);
                uint32_t byteOff = (uint32_t)(rA * SPITCH + kA) * 2;
                LDSM_X4(ah[mt][0], ah[mt][1], ah[mt][2], ah[mt][3], sAh + byteOff);
                LDSM_X4(al[mt][0], al[mt][1], al[mt][2], al[mt][3], sAl + byteOff);
            }
            uint32_t bh[8][2], bl[8][2];
#pragma unroll
            for (int p = 0; p < 4; p++) {
                int g = lane >> 3;
                int nB = warpN * 64 + p * 16 + ((g & 2) ? 8 : 0) + (lane & 7);
                int kB = s * 16 + ((g & 1) ? 8 : 0);
                uint32_t byteOff = (uint32_t)(nB * SPITCH + kB) * 2;
                LDSM_X4(bh[2*p][0], bh[2*p][1], bh[2*p+1][0], bh[2*p+1][1], sBh + byteOff);
                LDSM_X4(bl[2*p][0], bl[2*p][1], bl[2*p+1][0], bl[2*p+1][1], sBl + byteOff);
            }
#pragma unroll
            for (int mt = 0; mt < 2; mt++)
#pragma unroll
                for (int nt = 0; nt < 8; nt++) {
                    MMA_BF16(acc[mt][nt], ah[mt], bh[nt]);
                    MMA_BF16(acc[mt][nt], ah[mt], bl[nt]);
                    MMA_BF16(acc[mt][nt], al[mt], bh[nt]);
                }
        }
        __syncthreads();
    }

    // ---- epilogue: rowbias, store, fused attention dots ----
    if (rowbias) {
#pragma unroll
        for (int nt = 0; nt < 8; nt++) {
            int col = colBase + warpN * 64 + nt * 8 + (lane & 3) * 2;
            float b0 = rowbias[col], b1 = rowbias[col + 1];
#pragma unroll
            for (int mt = 0; mt < 2; mt++) {
                acc[mt][nt][0] += b0; acc[mt][nt][1] += b1;
                acc[mt][nt][2] += b0; acc[mt][nt][3] += b1;
            }
        }
    }
#pragma unroll
    for (int mt = 0; mt < 2; mt++) {
        int r0 = rowBase + warpM * 32 + mt * 16 + (lane >> 2);
#pragma unroll
        for (int half = 0; half < 2; half++) {
            int row = r0 + half * 8;
            if (row >= M) continue;
#pragma unroll
            for (int nt = 0; nt < 8; nt++) {
                int col = colBase + warpN * 64 + nt * 8 + (lane & 3) * 2;
                *(float2*)(C + (size_t)row * 256 + col) =
                    make_float2(acc[mt][nt][half * 2], acc[mt][nt][half * 2 + 1]);
            }
        }
    }
    // attention: this warp's 64 cols == head h's span (HH=256, grid.x=2, warpN in {0,1})
    {
        int h = (colBase >> 6) + warpN;
        const float* As_v = atts + h * 64;
        const float* Ad_v = attd + h * 64;
#pragma unroll
        for (int mt = 0; mt < 2; mt++) {
#pragma unroll
            for (int half = 0; half < 2; half++) {
                float ds = 0.f, dd = 0.f;
#pragma unroll
                for (int nt = 0; nt < 8; nt++) {
                    int cw = nt * 8 + (lane & 3) * 2;
                    float v0 = acc[mt][nt][half * 2], v1 = acc[mt][nt][half * 2 + 1];
                    ds += v0 * As_v[cw] + v1 * As_v[cw + 1];
                    dd += v0 * Ad_v[cw] + v1 * Ad_v[cw + 1];
                }
                ds += __shfl_xor_sync(0xffffffffu, ds, 1);
                ds += __shfl_xor_sync(0xffffffffu, ds, 2);
                dd += __shfl_xor_sync(0xffffffffu, dd, 1);
                dd += __shfl_xor_sync(0xffffffffu, dd, 2);
                int row = rowBase + warpM * 32 + mt * 16 + half * 8 + (lane >> 2);
                if ((lane & 3) == 0 && row < M) {
                    g_asrc[row * HEADS + h] = ds;
                    g_adst[row * HEADS + h] = dd;
                }
            }
        }
    }
}

// ---------------- CSR build ----------------
__global__ void k_deginit(int n) {
    int i = blockIdx.x * blockDim.x + threadIdx.x;
    if (i < n) g_deg[i] = 1;
}
__global__ void k_hist(const int* __restrict__ dstp, int E) {
    int i = blockIdx.x * blockDim.x + threadIdx.x;
    if (i < E) atomicAdd(&g_deg[dstp[i]], 1);
}
__global__ void k_scan1(int n) {
    __shared__ int sh[256];
    int tid = threadIdx.x;
    int i = blockIdx.x * 256 + tid;
    int v = (i < n) ? g_deg[i] : 0;
    sh[tid] = v; __syncthreads();
    for (int off = 1; off < 256; off <<= 1) {
        int t = (tid >= off) ? sh[tid - off] : 0;
        __syncthreads();
        sh[tid] += t;
        __syncthreads();
    }
    if (i < n) g_rowptr[i] = sh[tid] - v;
    if (tid == 255) g_bsums[blockIdx.x] = sh[255];
}
__global__ void k_scan2(int nb) {
    __shared__ int sh[256];
    int tid = threadIdx.x;
    int v = (tid < nb) ? g_bsums[tid] : 0;
    sh[tid] = v; __syncthreads();
    for (int off = 1; off < 256; off <<= 1) {
        int t = (tid >= off) ? sh[tid - off] : 0;
        __syncthreads();
        sh[tid] += t;
        __syncthreads();
    }
    if (tid < nb) g_bsums[tid] = sh[tid] - v;
}
__global__ void k_scan3(int n) {
    int i = blockIdx.x * 256 + threadIdx.x;
    if (i < n) {
        int r = g_rowptr[i] + g_bsums[blockIdx.x];
        g_rowptr[i] = r;
        g_cursor[i] = r;
    }
}
__global__ void k_scatter(const int* __restrict__ srcp, const int* __restrict__ dstp,
                          int E, int n) {
    int i = blockIdx.x * blockDim.x + threadIdx.x;
    int Et = E + n;
    if (i >= Et) return;
    int s, d;
    if (i < E) { s = srcp[i]; d = dstp[i]; }
    else       { s = d = i - E; }
    int pos = atomicAdd(&g_cursor[d], 1);
    g_csr[pos] = s;
}

// ---------------- gather aggregation: warp per dst node (R8 version) ----------------
template <int LAYER>
__global__ void k_gather(const float* __restrict__ bias, float* __restrict__ out, int n) {
    int d = (blockIdx.x * blockDim.x + threadIdx.x) >> 5;
    int lane = threadIdx.x & 31;
    if (d >= n) return;

    float adv = 0.f;
    if (lane < HEADS) adv = g_adst[d * HEADS + lane];

    int e   = g_rowptr[d];
    int end = g_cursor[d];

    float acc[8] = {};
    float den = 0.f;
#pragma unroll 2
    for (; e < end; e++) {
        int s = g_csr[e];
        float wl = 0.f;
        if (lane < HEADS) {
            float a = g_asrc[s * HEADS + lane] + adv;
            a = (a > 0.f) ? a : NEG * a;
            wl = __expf(a);
            den += wl;
        }
        const float* hr = g_hl + (size_t)s * HH;
#pragma unroll
        for (int h = 0; h < HEADS; h++) {
            float wh = __shfl_sync(0xffffffffu, wl, h);
            acc[2*h]   += wh * __ldg(hr + h * 64 + lane);
            acc[2*h+1] += wh * __ldg(hr + h * 64 + 32 + lane);
        }
    }
    float dv[4];
#pragma unroll
    for (int h = 0; h < HEADS; h++) dv[h] = __shfl_sync(0xffffffffu, den, h);

    if (LAYER == 1) {
        float* orow = g_agg + (size_t)d * HH;
#pragma unroll
        for (int h = 0; h < HEADS; h++) {
            int c0 = h * 64 + lane;
            orow[c0]      = acc[2*h]   / dv[h] + bias[c0];
            orow[c0 + 32] = acc[2*h+1] / dv[h] + bias[c0 + 32];
        }
    } else {
        float v0 = 0.f, v1 = 0.f;
#pragma unroll
        for (int h = 0; h < HEADS; h++) {
            v0 += acc[2*h]   / dv[h];
            v1 += acc[2*h+1] / dv[h];
        }
        out[d * HID + lane]      = 0.25f * v0 + bias[lane];
        out[d * HID + lane + 32] = 0.25f * v1 + bias[lane + 32];
    }
}

// BN2 normalize + ReLU -> split bf16 (feeds GEMM2 directly)
__global__ void k_bnrelu(const float* __restrict__ beta, int n) {
    size_t i = (size_t)blockIdx.x * blockDim.x + threadIdx.x;
    if (i >= (size_t)n * HH) return;
    int c = (int)(i & 255);
    float v = (g_agg[i] - g_mean[c]) * g_scale[c] + beta[c];
    v = (v > 0.f) ? v : 0.f;
    uint16_t h, l;
    splitf(v, h, l);
    g_h2h[i] = h;
    g_h2l[i] = l;
}

// ---------------- host launcher ----------------
extern "C" void kernel_launch(void* const* d_in, const int* in_sizes, int n_in,
                              void* d_out, int out_size) {
    const float* x        = (const float*)d_in[0];
    const int*   ei       = (const int*)d_in[1];      // int32 (JAX x64 disabled)
    const float* gamma1   = (const float*)d_in[2];
    const float* beta1    = (const float*)d_in[3];
    const float* W1       = (const float*)d_in[4];
    const float* att_src1 = (const float*)d_in[5];
    const float* att_dst1 = (const float*)d_in[6];
    const float* bias1    = (const float*)d_in[7];
    const float* gamma2   = (const float*)d_in[8];
    const float* beta2    = (const float*)d_in[9];
    const float* W2       = (const float*)d_in[10];
    const float* att_src2 = (const float*)d_in[11];
    const float* att_dst2 = (const float*)d_in[12];
    const float* bias2    = (const float*)d_in[13];

    int n = in_sizes[0] / INDIM;
    int E = in_sizes[1] / 2;
    const int* srcp = ei;
    const int* dstp = ei + E;
    float* out = (float*)d_out;

    float *p_hl, *p_agg, *p_sums, *p_scale, *p_rowbias;
    cudaGetSymbolAddress((void**)&p_hl,      g_hl);
    cudaGetSymbolAddress((void**)&p_agg,     g_agg);
    cudaGetSymbolAddress((void**)&p_sums,    g_sums);
    cudaGetSymbolAddress((void**)&p_scale,   g_scale);
    cudaGetSymbolAddress((void**)&p_rowbias, g_rowbias);
    uint16_t *p_xh, *p_xl, *p_h2h, *p_h2l;
    cudaGetSymbolAddress((void**)&p_xh,  g_xh);
    cudaGetSymbolAddress((void**)&p_xl,  g_xl);
    cudaGetSymbolAddress((void**)&p_h2h, g_h2h);
    cudaGetSymbolAddress((void**)&p_h2l, g_h2l);

    int Et = E + n;
    int featElems = n * HH;
    int scanBlocks = (n + 255) / 256;
    dim3 gemmGrid(2, (n + 127) / 128);

    // ---- CSR build ----
    k_deginit<<<scanBlocks, 256>>>(n);
    k_hist<<<(E + 255) / 256, 256>>>(dstp, E);
    k_scan1<<<scanBlocks, 256>>>(n);
    k_scan2<<<1, 256>>>(scanBlocks);
    k_scan3<<<scanBlocks, 256>>>(n);
    k_scatter<<<(Et + 255) / 256, 256>>>(srcp, dstp, E, n);

    // ---- BN1 stats (folded into GEMM1 via W colscale + rowbias) ----
    k_clear<<<2, 256>>>(p_sums, 512);
    k_colstats<<<512, INDIM>>>(x, n, INDIM, p_sums, p_sums + 256);
    k_bnfinal<<<1, INDIM>>>(gamma1, beta1, INDIM, n, 1);
    k_rowbias<<<HH, 128>>>(W1, INDIM);

    // ---- GAT1 ----
    k_prepx<<<(n * INDIM + 255) / 256, 256>>>(x, n * INDIM);
    k_prepw<<<(256 * INDIM + 255) / 256, 256>>>(W1, INDIM, p_scale);
    k_mmagemm<<<gemmGrid, 256>>>(p_xh, p_xl, p_hl, n, INDIM,
                                 p_rowbias, att_src1, att_dst1);
    k_gather<1><<<(n * 32 + 255) / 256, 256>>>(bias1, nullptr, n);

    // ---- BN2 + ReLU (stats over g_agg, then normalize -> split bf16) ----
    k_clear<<<2, 256>>>(p_sums, 512);
    k_colstats<<<512, HH>>>(p_agg, n, HH, p_sums, p_sums + 256);
    k_bnfinal<<<1, HH>>>(gamma2, beta2, HH, n, 0);
    k_bnrelu<<<(featElems + 255) / 256, 256>>>(beta2, n);

    // ---- GAT2 ----
    k_prepw<<<(256 * HH + 255) / 256, 256>>>(W2, HH, nullptr);
    k_mmagemm<<<gemmGrid, 256>>>(p_h2h, p_h2l, p_hl, n, HH,
                                 nullptr, att_src2, att_dst2);
    k_gather<2><<<(n * 32 + 255) / 256, 256>>>(bias2, out, n);
}

// round 14
// speedup vs baseline: 1.4079x; 1.1368x over previous
#include <cuda_runtime.h>
#include <cuda_bf16.h>
#include <cuda_fp16.h>
#include <cstdint>

#define NODES   50000
#define MAXE    800000
#define INDIM   128
#define HH      256     // HEADS*HIDDEN
#define HEADS   4
#define HID     64
#define EPSV    1e-5f
#define NEG     0.2f

// ---------------- PTX helpers (base sm_103-safe) ----------------
__device__ __forceinline__ uint32_t smem_to_u32(const void* p) {
    uint32_t a;
    asm("{ .reg .u64 t; cvta.to.shared.u64 t, %1; cvt.u32.u64 %0, t; }" : "=r"(a) : "l"(p));
    return a;
}
#define LDSM_X4(r0, r1, r2, r3, addr) \
    asm volatile("ldmatrix.sync.aligned.m8n8.x4.shared.b16 {%0,%1,%2,%3}, [%4];" \
        : "=r"(r0), "=r"(r1), "=r"(r2), "=r"(r3) : "r"(addr))
#define MMA_BF16(d, a, b) \
    asm volatile("mma.sync.aligned.m16n8k16.row.col.f32.bf16.bf16.f32 " \
        "{%0,%1,%2,%3}, {%4,%5,%6,%7}, {%8,%9}, {%0,%1,%2,%3};" \
        : "+f"((d)[0]), "+f"((d)[1]), "+f"((d)[2]), "+f"((d)[3]) \
        : "r"((a)[0]), "r"((a)[1]), "r"((a)[2]), "r"((a)[3]), "r"((b)[0]), "r"((b)[1]))

// -------- device scratch (no allocation allowed) --------
__device__ uint32_t g_hlh[NODES * 128];     // hl as packed half2 (cols 2i, 2i+1)
__device__ float g_agg[NODES * HH];
__device__ float g_asrc[NODES * HEADS];
__device__ float g_adst[NODES * HEADS];
__device__ float g_sums[512];
__device__ float g_scale[256];
__device__ float g_shift[256];
__device__ float g_mean[256];
__device__ float g_rowbias[256];
__device__ uint16_t g_Wt_hi[256 * 256];     // W^T split bf16 hi [n][k]
__device__ uint16_t g_Wt_lo[256 * 256];     // bf16 lo residual  [n][k]
__device__ uint16_t g_xh[NODES * INDIM];    // x split hi
__device__ uint16_t g_xl[NODES * INDIM];    // x split lo
__device__ uint16_t g_h2h[NODES * HH];      // post-BN2+ReLU split hi
__device__ uint16_t g_h2l[NODES * HH];      // split lo
// CSR build scratch
__device__ int g_deg[NODES];
__device__ int g_rowptr[NODES];
__device__ int g_cursor[NODES];
__device__ int g_bsums[256];
__device__ int g_csr[MAXE + NODES];

// ---------------- utility kernels ----------------
__global__ void k_clear(float* __restrict__ p, int n) {
    int i = blockIdx.x * blockDim.x + threadIdx.x;
    if (i < n) p[i] = 0.f;
}

__global__ void k_colstats(const float* __restrict__ x, int n, int C,
                           float* __restrict__ sums, float* __restrict__ sumsq) {
    int c = threadIdx.x;
    float s = 0.f, s2 = 0.f;
    for (int r = blockIdx.x; r < n; r += gridDim.x) {
        float v = x[(size_t)r * C + c];
        s += v; s2 += v * v;
    }
    atomicAdd(&sums[c], s);
    atomicAdd(&sumsq[c], s2);
}

__global__ void k_bnfinal(const float* __restrict__ gamma, const float* __restrict__ beta,
                          int C, int n, int fold) {
    int c = threadIdx.x;
    if (c >= C) return;
    float mean = g_sums[c] / (float)n;
    float var  = g_sums[256 + c] / (float)n - mean * mean;
    float sc   = rsqrtf(var + EPSV) * gamma[c];
    g_scale[c] = sc;
    if (fold) g_shift[c] = beta[c] - mean * sc;
    else      g_mean[c]  = mean;
}

__global__ void k_rowbias(const float* __restrict__ W, int K) {
    __shared__ float sh[128];
    int j = blockIdx.x, t = threadIdx.x;
    float s = 0.f;
    for (int k = t; k < K; k += 128) s += g_shift[k] * W[(size_t)k * HH + j];
    sh[t] = s; __syncthreads();
    for (int off = 64; off; off >>= 1) { if (t < off) sh[t] += sh[t + off]; __syncthreads(); }
    if (t == 0) g_rowbias[j] = sh[0];
}

// ---------------- split helpers ----------------
__device__ __forceinline__ void splitf(float x, uint16_t& h, uint16_t& l) {
    __nv_bfloat16 bh = __float2bfloat16(x);
    float r = x - __bfloat162float(bh);
    __nv_bfloat16 bl = __float2bfloat16(r);
    h = __bfloat16_as_ushort(bh);
    l = __bfloat16_as_ushort(bl);
}

__global__ void k_prepw(const float* __restrict__ W, int K, const float* __restrict__ colscale) {
    int idx = blockIdx.x * blockDim.x + threadIdx.x;   // idx = n*K + k
    if (idx >= 256 * K) return;
    int n = idx / K, k = idx - n * K;
    float v = W[(size_t)k * 256 + n];
    if (colscale) v *= colscale[k];
    uint16_t h, l;
    splitf(v, h, l);
    g_Wt_hi[idx] = h;
    g_Wt_lo[idx] = l;
}

__global__ void k_prepx(const float* __restrict__ x, int total) {
    int i = blockIdx.x * blockDim.x + threadIdx.x;
    if (i >= total) return;
    uint16_t h, l;
    splitf(x[i], h, l);
    g_xh[i] = h;
    g_xl[i] = l;
}

// ---------------- HMMA GEMM (static smem, sync staging, 5 CTAs/SM) ----------------
// Inputs pre-split bf16 hi/lo. Writes hl as packed half2 (gather-only consumer);
// attn dots computed from fp32 accumulators in epilogue.
#define SPITCH 40

__global__ __launch_bounds__(256)
void k_mmagemm(const uint16_t* __restrict__ Ah, const uint16_t* __restrict__ Al,
               uint32_t* __restrict__ Chl, int M, int K,
               const float* __restrict__ rowbias,
               const float* __restrict__ atts, const float* __restrict__ attd) {
    __shared__ __align__(16) uint16_t As_hi[128 * SPITCH];
    __shared__ __align__(16) uint16_t As_lo[128 * SPITCH];
    __shared__ __align__(16) uint16_t Bs_hi[128 * SPITCH];
    __shared__ __align__(16) uint16_t Bs_lo[128 * SPITCH];

    const int tid = threadIdx.x, lane = tid & 31, wid = tid >> 5;
    const int warpM = wid >> 1, warpN = wid & 1;
    const int rowBase = blockIdx.y * 128;
    const int colBase = blockIdx.x * 128;

    const uint32_t sAh = smem_to_u32(As_hi), sAl = smem_to_u32(As_lo);
    const uint32_t sBh = smem_to_u32(Bs_hi), sBl = smem_to_u32(Bs_lo);

    float acc[2][8][4] = {};

    for (int k0 = 0; k0 < K; k0 += 32) {
        for (int i = tid; i < 128 * 8; i += 256) {
            int r = i >> 3, q = i & 7;
            int gr = rowBase + r;
            uint2 vh = make_uint2(0u, 0u), vl = make_uint2(0u, 0u);
            if (gr < M) {
                size_t gofs = (size_t)gr * K + k0 + q * 4;
                vh = *(const uint2*)(Ah + gofs);
                vl = *(const uint2*)(Al + gofs);
            }
            int off = r * SPITCH + q * 4;
            *(uint2*)(As_hi + off) = vh;
            *(uint2*)(As_lo + off) = vl;
        }
        for (int i = tid; i < 128 * 8; i += 256) {
            int n = i >> 3, q = i & 7;
            size_t gofs = (size_t)(colBase + n) * K + k0 + q * 4;
            uint2 vh = *(const uint2*)(g_Wt_hi + gofs);
            uint2 vl = *(const uint2*)(g_Wt_lo + gofs);
            int off = n * SPITCH + q * 4;
            *(uint2*)(Bs_hi + off) = vh;
            *(uint2*)(Bs_lo + off) = vl;
        }
        __syncthreads();

#pragma unroll
        for (int s = 0; s < 2; s++) {
            uint32_t ah[2][4], al[2][4];
#pragma unroll
            for (int mt = 0; mt < 2; mt++) {
                int rA = warpM * 32 + mt * 16 + (lane & 15);
                int kA = s * 16 + ((lane & 16) ? 8 : 0);
                uint32_t byteOff = (uint32_t)(rA * SPITCH + kA) * 2;
                LDSM_X4(ah[mt][0], ah[mt][1], ah[mt][2], ah[mt][3], sAh + byteOff);
                LDSM_X4(al[mt][0], al[mt][1], al[mt][2], al[mt][3], sAl + byteOff);
            }
            uint32_t bh[8][2], bl[8][2];
#pragma unroll
            for (int p = 0; p < 4; p++) {
                int g = lane >> 3;
                int nB = warpN * 64 + p * 16 + ((g & 2) ? 8 : 0) + (lane & 7);
                int kB = s * 16 + ((g & 1) ? 8 : 0);
                uint32_t byteOff = (uint32_t)(nB * SPITCH + kB) * 2;
                LDSM_X4(bh[2*p][0], bh[2*p][1], bh[2*p+1][0], bh[2*p+1][1], sBh + byteOff);
                LDSM_X4(bl[2*p][0], bl[2*p][1], bl[2*p+1][0], bl[2*p+1][1], sBl + byteOff);
            }
#pragma unroll
            for (int mt = 0; mt < 2; mt++)
#pragma unroll
                for (int nt = 0; nt < 8; nt++) {
                    MMA_BF16(acc[mt][nt], ah[mt], bh[nt]);
                    MMA_BF16(acc[mt][nt], ah[mt], bl[nt]);
                    MMA_BF16(acc[mt][nt], al[mt], bh[nt]);
                }
        }
        __syncthreads();
    }

    // ---- epilogue: rowbias, half2 store, fused attention dots ----
    if (rowbias) {
#pragma unroll
        for (int nt = 0; nt < 8; nt++) {
            int col = colBase + warpN * 64 + nt * 8 + (lane & 3) * 2;
            float b0 = rowbias[col], b1 = rowbias[col + 1];
#pragma unroll
            for (int mt = 0; mt < 2; mt++) {
                acc[mt][nt][0] += b0; acc[mt][nt][1] += b1;
                acc[mt][nt][2] += b0; acc[mt][nt][3] += b1;
            }
        }
    }
#pragma unroll
    for (int mt = 0; mt < 2; mt++) {
        int r0 = rowBase + warpM * 32 + mt * 16 + (lane >> 2);
#pragma unroll
        for (int half = 0; half < 2; half++) {
            int row = r0 + half * 8;
            if (row >= M) continue;
#pragma unroll
            for (int nt = 0; nt < 8; nt++) {
                int col = colBase + warpN * 64 + nt * 8 + (lane & 3) * 2;  // even
                __half2 hv = __floats2half2_rn(acc[mt][nt][half * 2], acc[mt][nt][half * 2 + 1]);
                Chl[(size_t)row * 128 + (col >> 1)] = *(uint32_t*)&hv;
            }
        }
    }
    // attention dots from fp32 accumulators (head h = this warp's 64-col span)
    {
        int h = (colBase >> 6) + warpN;
        const float* As_v = atts + h * 64;
        const float* Ad_v = attd + h * 64;
#pragma unroll
        for (int mt = 0; mt < 2; mt++) {
#pragma unroll
            for (int half = 0; half < 2; half++) {
                float ds = 0.f, dd = 0.f;
#pragma unroll
                for (int nt = 0; nt < 8; nt++) {
                    int cw = nt * 8 + (lane & 3) * 2;
                    float v0 = acc[mt][nt][half * 2], v1 = acc[mt][nt][half * 2 + 1];
                    ds += v0 * As_v[cw] + v1 * As_v[cw + 1];
                    dd += v0 * Ad_v[cw] + v1 * Ad_v[cw + 1];
                }
                ds += __shfl_xor_sync(0xffffffffu, ds, 1);
                ds += __shfl_xor_sync(0xffffffffu, ds, 2);
                dd += __shfl_xor_sync(0xffffffffu, dd, 1);
                dd += __shfl_xor_sync(0xffffffffu, dd, 2);
                int row = rowBase + warpM * 32 + mt * 16 + half * 8 + (lane >> 2);
                if ((lane & 3) == 0 && row < M) {
                    g_asrc[row * HEADS + h] = ds;
                    g_adst[row * HEADS + h] = dd;
                }
            }
        }
    }
}

// ---------------- CSR build ----------------
__global__ void k_deginit(int n) {
    int i = blockIdx.x * blockDim.x + threadIdx.x;
    if (i < n) g_deg[i] = 1;
}
__global__ void k_hist(const int* __restrict__ dstp, int E) {
    int i = blockIdx.x * blockDim.x + threadIdx.x;
    if (i < E) atomicAdd(&g_deg[dstp[i]], 1);
}
__global__ void k_scan1(int n) {
    __shared__ int sh[256];
    int tid = threadIdx.x;
    int i = blockIdx.x * 256 + tid;
    int v = (i < n) ? g_deg[i] : 0;
    sh[tid] = v; __syncthreads();
    for (int off = 1; off < 256; off <<= 1) {
        int t = (tid >= off) ? sh[tid - off] : 0;
        __syncthreads();
        sh[tid] += t;
        __syncthreads();
    }
    if (i < n) g_rowptr[i] = sh[tid] - v;
    if (tid == 255) g_bsums[blockIdx.x] = sh[255];
}
__global__ void k_scan2(int nb) {
    __shared__ int sh[256];
    int tid = threadIdx.x;
    int v = (tid < nb) ? g_bsums[tid] : 0;
    sh[tid] = v; __syncthreads();
    for (int off = 1; off < 256; off <<= 1) {
        int t = (tid >= off) ? sh[tid - off] : 0;
        __syncthreads();
        sh[tid] += t;
        __syncthreads();
    }
    if (tid < nb) g_bsums[tid] = sh[tid] - v;
}
__global__ void k_scan3(int n) {
    int i = blockIdx.x * 256 + threadIdx.x;
    if (i < n) {
        int r = g_rowptr[i] + g_bsums[blockIdx.x];
        g_rowptr[i] = r;
        g_cursor[i] = r;
    }
}
__global__ void k_scatter(const int* __restrict__ srcp, const int* __restrict__ dstp,
                          int E, int n) {
    int i = blockIdx.x * blockDim.x + threadIdx.x;
    int Et = E + n;
    if (i >= Et) return;
    int s, d;
    if (i < E) { s = srcp[i]; d = dstp[i]; }
    else       { s = d = i - E; }
    int pos = atomicAdd(&g_cursor[d], 1);
    g_csr[pos] = s;
}

// ---------------- gather aggregation: warp per dst node, fp16 features ----------------
// lane owns cols {2*lane, 2*lane+1} of each head.
template <int LAYER>
__global__ void k_gather(const float* __restrict__ bias, float* __restrict__ out, int n) {
    int d = (blockIdx.x * blockDim.x + threadIdx.x) >> 5;
    int lane = threadIdx.x & 31;
    if (d >= n) return;

    float adv = 0.f;
    if (lane < HEADS) adv = g_adst[d * HEADS + lane];

    int e   = g_rowptr[d];
    int end = g_cursor[d];

    float acc[8] = {};
    float den = 0.f;
#pragma unroll 2
    for (; e < end; e++) {
        int s = g_csr[e];
        float wl = 0.f;
        if (lane < HEADS) {
            float a = g_asrc[s * HEADS + lane] + adv;
            a = (a > 0.f) ? a : NEG * a;
            wl = __expf(a);
            den += wl;
        }
        const uint32_t* hr = g_hlh + (size_t)s * 128;
#pragma unroll
        for (int h = 0; h < HEADS; h++) {
            float wh = __shfl_sync(0xffffffffu, wl, h);
            uint32_t p = __ldg(hr + h * 32 + lane);
            float2 f = __half22float2(*(__half2*)&p);
            acc[2*h]   += wh * f.x;
            acc[2*h+1] += wh * f.y;
        }
    }
    float dv[4];
#pragma unroll
    for (int h = 0; h < HEADS; h++) dv[h] = __shfl_sync(0xffffffffu, den, h);

    if (LAYER == 1) {
        float* orow = g_agg + (size_t)d * HH;
#pragma unroll
        for (int h = 0; h < HEADS; h++) {
            int c0 = h * 64 + 2 * lane;
            orow[c0]     = acc[2*h]   / dv[h] + bias[c0];
            orow[c0 + 1] = acc[2*h+1] / dv[h] + bias[c0 + 1];
        }
    } else {
        float v0 = 0.f, v1 = 0.f;
#pragma unroll
        for (int h = 0; h < HEADS; h++) {
            v0 += acc[2*h]   / dv[h];
            v1 += acc[2*h+1] / dv[h];
        }
        int c0 = 2 * lane;
        out[d * HID + c0]     = 0.25f * v0 + bias[c0];
        out[d * HID + c0 + 1] = 0.25f * v1 + bias[c0 + 1];
    }
}

// BN2 normalize + ReLU -> split bf16 (feeds GEMM2 directly)
__global__ void k_bnrelu(const float* __restrict__ beta, int n) {
    size_t i = (size_t)blockIdx.x * blockDim.x + threadIdx.x;
    if (i >= (size_t)n * HH) return;
    int c = (int)(i & 255);
    float v = (g_agg[i] - g_mean[c]) * g_scale[c] + beta[c];
    v = (v > 0.f) ? v : 0.f;
    uint16_t h, l;
    splitf(v, h, l);
    g_h2h[i] = h;
    g_h2l[i] = l;
}

// ---------------- host launcher ----------------
extern "C" void kernel_launch(void* const* d_in, const int* in_sizes, int n_in,
                              void* d_out, int out_size) {
    const float* x        = (const float*)d_in[0];
    const int*   ei       = (const int*)d_in[1];      // int32 (JAX x64 disabled)
    const float* gamma1   = (const float*)d_in[2];
    const float* beta1    = (const float*)d_in[3];
    const float* W1       = (const float*)d_in[4];
    const float* att_src1 = (const float*)d_in[5];
    const float* att_dst1 = (const float*)d_in[6];
    const float* bias1    = (const float*)d_in[7];
    const float* gamma2   = (const float*)d_in[8];
    const float* beta2    = (const float*)d_in[9];
    const float* W2       = (const float*)d_in[10];
    const float* att_src2 = (const float*)d_in[11];
    const float* att_dst2 = (const float*)d_in[12];
    const float* bias2    = (const float*)d_in[13];

    int n = in_sizes[0] / INDIM;
    int E = in_sizes[1] / 2;
    const int* srcp = ei;
    const int* dstp = ei + E;
    float* out = (float*)d_out;

    float *p_agg, *p_sums, *p_scale, *p_rowbias;
    cudaGetSymbolAddress((void**)&p_agg,     g_agg);
    cudaGetSymbolAddress((void**)&p_sums,    g_sums);
    cudaGetSymbolAddress((void**)&p_scale,   g_scale);
    cudaGetSymbolAddress((void**)&p_rowbias, g_rowbias);
    uint32_t* p_hlh;
    cudaGetSymbolAddress((void**)&p_hlh, g_hlh);
    uint16_t *p_xh, *p_xl, *p_h2h, *p_h2l;
    cudaGetSymbolAddress((void**)&p_xh,  g_xh);
    cudaGetSymbolAddress((void**)&p_xl,  g_xl);
    cudaGetSymbolAddress((void**)&p_h2h, g_h2h);
    cudaGetSymbolAddress((void**)&p_h2l, g_h2l);

    int Et = E + n;
    int featElems = n * HH;
    int scanBlocks = (n + 255) / 256;
    dim3 gemmGrid(2, (n + 127) / 128);

    // ---- CSR build ----
    k_deginit<<<scanBlocks, 256>>>(n);
    k_hist<<<(E + 255) / 256, 256>>>(dstp, E);
    k_scan1<<<scanBlocks, 256>>>(n);
    k_scan2<<<1, 256>>>(scanBlocks);
    k_scan3<<<scanBlocks, 256>>>(n);
    k_scatter<<<(Et + 255) / 256, 256>>>(srcp, dstp, E, n);

    // ---- BN1 stats (folded into GEMM1 via W colscale + rowbias) ----
    k_clear<<<2, 256>>>(p_sums, 512);
    k_colstats<<<512, INDIM>>>(x, n, INDIM, p_sums, p_sums + 256);
    k_bnfinal<<<1, INDIM>>>(gamma1, beta1, INDIM, n, 1);
    k_rowbias<<<HH, 128>>>(W1, INDIM);

    // ---- GAT1 ----
    k_prepx<<<(n * INDIM + 255) / 256, 256>>>(x, n * INDIM);
    k_prepw<<<(256 * INDIM + 255) / 256, 256>>>(W1, INDIM, p_scale);
    k_mmagemm<<<gemmGrid, 256>>>(p_xh, p_xl, p_hlh, n, INDIM,
                                 p_rowbias, att_src1, att_dst1);
    k_gather<1><<<(n * 32 + 255) / 256, 256>>>(bias1, nullptr, n);

    // ---- BN2 + ReLU (stats over g_agg, then normalize -> split bf16) ----
    k_clear<<<2, 256>>>(p_sums, 512);
    k_colstats<<<512, HH>>>(p_agg, n, HH, p_sums, p_sums + 256);
    k_bnfinal<<<1, HH>>>(gamma2, beta2, HH, n, 0);
    k_bnrelu<<<(featElems + 255) / 256, 256>>>(beta2, n);

    // ---- GAT2 ----
    k_prepw<<<(256 * HH + 255) / 256, 256>>>(W2, HH, nullptr);
    k_mmagemm<<<gemmGrid, 256>>>(p_h2h, p_h2l, p_hlh, n, HH,
                                 nullptr, att_src2, att_dst2);
    k_gather<2><<<(n * 32 + 255) / 256, 256>>>(bias2, out, n);
}